// round 1
// baseline (speedup 1.0000x reference)
#include <cuda_runtime.h>

#define BB 32
#define NN 300
#define HH 1024
#define WW 1024
#define HWP (HH * WW)
#define NB (BB * NN)          // 9600 boxes total
#define ROWS_PER_BLK 8
#define THREADS 256
#define NWARPS (THREADS / 32)

// Scratch (no allocations allowed): per-box accumulators + metadata.
__device__ float g_boxsum[NB];
__device__ int4  g_coord[NB];    // x1, x2, y1, y2  (invalid boxes -> all zero)
__device__ float g_wscale[NB];   // valid ? conf/area : 0

// ---------------------------------------------------------------------------
// Kernel 1: per-box prep (coords, validity, weight) + zero accumulators.
// Runs every launch so graph replays start from a clean state.
// ---------------------------------------------------------------------------
__global__ void prep_kernel(const float* __restrict__ boxes,
                            const float* __restrict__ conf) {
    int i = blockIdx.x * blockDim.x + threadIdx.x;
    if (i >= NB) return;
    float cx = boxes[i * 4 + 0];
    float cy = boxes[i * 4 + 1];
    float w  = boxes[i * 4 + 2];
    float h  = boxes[i * 4 + 3];
    float c  = conf[i];

    // (v*dim) trunc toward zero (C cast == jnp.trunc for our range), clamp.
    int x1 = min(max((int)((cx - 0.5f * w) * (float)WW), 0), WW - 1);
    int x2 = min(max((int)((cx + 0.5f * w) * (float)WW), 0), WW - 1);
    int y1 = min(max((int)((cy - 0.5f * h) * (float)HH), 0), HH - 1);
    int y2 = min(max((int)((cy + 0.5f * h) * (float)HH), 0), HH - 1);

    bool valid = (c >= 0.3f) && (x2 > x1) && (y2 > y1);
    float area = (float)((y2 - y1) * (x2 - x1));
    if (!valid) { x1 = x2 = y1 = y2 = 0; }

    g_coord[i]  = make_int4(x1, x2, y1, y2);
    g_wscale[i] = valid ? (c / area) : 0.0f;
    g_boxsum[i] = 0.0f;
}

// ---------------------------------------------------------------------------
// Kernel 2: stream both mask channels once. One CTA handles an 8-row strip
// of one image: per row, build the exclusive row prefix of (footpath -
// driveway) in SMEM, then each thread adds S[x2]-S[x1] for its owned boxes
// (thread t owns boxes t and t+256 -> register accumulation, no SMEM races).
// ---------------------------------------------------------------------------
__global__ __launch_bounds__(THREADS)
void strip_kernel(const float* __restrict__ seg) {
    __shared__ float S[WW + 1];        // exclusive prefix: S[x] = sum_{c<x} diff
    __shared__ float warpsum[NWARPS];

    const int b    = blockIdx.x / (HH / ROWS_PER_BLK);
    const int rb   = blockIdx.x % (HH / ROWS_PER_BLK);
    const int row0 = rb * ROWS_PER_BLK;
    const int tid  = threadIdx.x;
    const int lane = tid & 31;
    const int wid  = tid >> 5;

    // Owned boxes (<=2 per thread).
    const int n0 = tid;
    const int n1 = tid + THREADS;
    int4 c0 = (n0 < NN) ? g_coord[b * NN + n0] : make_int4(0, 0, 0, 0);
    int4 c1 = (n1 < NN) ? g_coord[b * NN + n1] : make_int4(0, 0, 0, 0);
    float acc0 = 0.0f, acc1 = 0.0f;

    const float4* dptr = (const float4*)(seg + (size_t)b * 3 * HWP + 1 * HWP);
    const float4* fptr = (const float4*)(seg + (size_t)b * 3 * HWP + 2 * HWP);

    // Software-pipelined row loads (prefetch next row while scanning current).
    float4 dd, ff;
    {
        int idx = row0 * (WW / 4) + tid;
        dd = dptr[idx];
        ff = fptr[idx];
    }

    #pragma unroll
    for (int r = 0; r < ROWS_PER_BLK; ++r) {
        const int row = row0 + r;

        float4 dv;
        dv.x = ff.x - dd.x; dv.y = ff.y - dd.y;
        dv.z = ff.z - dd.z; dv.w = ff.w - dd.w;

        float4 dd2, ff2;
        if (r + 1 < ROWS_PER_BLK) {
            int idx = (row + 1) * (WW / 4) + tid;
            dd2 = dptr[idx];
            ff2 = fptr[idx];
        }

        // Thread-local inclusive prefix over 4 elements.
        float p0 = dv.x;
        float p1 = p0 + dv.y;
        float p2 = p1 + dv.z;
        float p3 = p2 + dv.w;

        // Warp-inclusive scan of per-thread sums.
        float t = p3;
        #pragma unroll
        for (int o = 1; o < 32; o <<= 1) {
            float v = __shfl_up_sync(0xffffffffu, t, o);
            if (lane >= o) t += v;
        }
        if (lane == 31) warpsum[wid] = t;
        __syncthreads();

        // Cross-warp exclusive base (8 warps -> tiny serial sum).
        float wbase = 0.0f;
        #pragma unroll
        for (int wv = 0; wv < NWARPS; ++wv)
            if (wv < wid) wbase += warpsum[wv];

        float base = wbase + (t - p3);   // exclusive prefix for this thread
        int xi = tid << 2;
        S[xi + 1] = base + p0;
        S[xi + 2] = base + p1;
        S[xi + 3] = base + p2;
        S[xi + 4] = base + p3;
        if (tid == 0) S[0] = 0.0f;
        __syncthreads();

        // Box accumulation for this row (register-resident, no conflicts).
        if (row >= c0.z && row < c0.w) acc0 += S[c0.y] - S[c0.x];
        if (row >= c1.z && row < c1.w) acc1 += S[c1.y] - S[c1.x];
        __syncthreads();   // protect S / warpsum before next row's scan

        dd = dd2;
        ff = ff2;
    }

    if (n0 < NN && acc0 != 0.0f) atomicAdd(&g_boxsum[b * NN + n0], acc0);
    if (n1 < NN && acc1 != 0.0f) atomicAdd(&g_boxsum[b * NN + n1], acc1);
}

// ---------------------------------------------------------------------------
// Kernel 3: final reduction over 9600 boxes -> scalar.
// ---------------------------------------------------------------------------
__global__ void reduce_kernel(float* __restrict__ out) {
    const int tid = threadIdx.x;
    float s = 0.0f;
    for (int i = tid; i < NB; i += THREADS) {
        float v = g_boxsum[i];
        s += fmaxf(v, 0.0f) * g_wscale[i];   // relu((f-d)/area)*conf
    }
    __shared__ float sm[NWARPS];
    #pragma unroll
    for (int o = 16; o > 0; o >>= 1) s += __shfl_down_sync(0xffffffffu, s, o);
    if ((tid & 31) == 0) sm[tid >> 5] = s;
    __syncthreads();
    if (tid < NWARPS) {
        s = sm[tid];
        #pragma unroll
        for (int o = NWARPS / 2; o > 0; o >>= 1)
            s += __shfl_down_sync(0xffu, s, o);
        if (tid == 0) out[0] = s / (float)NB;
    }
}

// ---------------------------------------------------------------------------
extern "C" void kernel_launch(void* const* d_in, const int* in_sizes, int n_in,
                              void* d_out, int out_size) {
    const float* boxes = (const float*)d_in[0];   // (32,300,4)
    const float* conf  = (const float*)d_in[1];   // (32,300)
    const float* seg   = (const float*)d_in[2];   // (32,3,1024,1024)
    float* out = (float*)d_out;

    prep_kernel<<<(NB + 255) / 256, 256>>>(boxes, conf);
    strip_kernel<<<BB * (HH / ROWS_PER_BLK), THREADS>>>(seg);
    reduce_kernel<<<1, THREADS>>>(out);
}